// round 5
// baseline (speedup 1.0000x reference)
#include <cuda_runtime.h>
#include <cstdint>

// Attention_18021682774359: BiDAF-style context-query attention.
// B=64, CL=400, QL=50, H=1024. Output [B, CL, 4H] fp32.
//
// Round 5: tensor-core GEMMs via mma.sync m16n8k8 tf32 with 3xTF32 accuracy.
// The hi/lo split is done with pure bit-masking (no cvt.rna.tf32 asm, which is
// the prime suspect for the round-3/4 container failures):
//   hi = x with low 13 mantissa bits zeroed  (exactly representable in tf32)
//   lo = x - hi                              (captures the truncated tail)
//   A*B ~= Ah*Bh + Ah*Bl + Al*Bh
// Operands staged in shared memory directly in mma fragment layout; hot loop =
// LDS.128 + HMMA only.

namespace {
constexpr int B_  = 64;
constexpr int CL_ = 400;
constexpr int QL_ = 50;
constexpr int H_  = 1024;
constexpr int QS_ = 64;   // padded QL
}

// -------- scratch (device globals; allocation-free) --------
__device__ float g_G   [B_*CL_*QS_];   // raw similarity GEMM part
__device__ float g_s1  [B_*CL_*QS_];   // softmax over q (cols 50..63 zero)
__device__ float g_s2  [B_*CL_*QS_];   // softmax over c (cols 50..63 zero)
__device__ float g_qpad[B_*QS_*H_];    // q zero-padded to 64 rows per batch
__device__ float g_t   [B_*QS_*H_];    // s2^T @ c, padded rows are zero
__device__ float g_cdot[B_*CL_];
__device__ float g_qdot[B_*QS_];

// -------- tf32 split helpers (pure C, no cvt asm) --------
__device__ __forceinline__ void split1(float x, unsigned& h, unsigned& l) {
    unsigned hu = __float_as_uint(x) & 0xFFFFE000u;   // keep 10 mantissa bits
    h = hu;
    l = __float_as_uint(x - __uint_as_float(hu));     // tail (tf32-rounded by HW)
}
__device__ __forceinline__ void mma8(float* d, uint4 a, unsigned b0, unsigned b1) {
    asm("mma.sync.aligned.m16n8k8.row.col.f32.tf32.tf32.f32 "
        "{%0,%1,%2,%3},{%4,%5,%6,%7},{%8,%9},{%0,%1,%2,%3};"
        : "+f"(d[0]), "+f"(d[1]), "+f"(d[2]), "+f"(d[3])
        : "r"(a.x), "r"(a.y), "r"(a.z), "r"(a.w), "r"(b0), "r"(b1));
}

// Fragment-layout addressing (m16n8k8, K-chunk=32 -> 4 k-steps):
//  A element (m-row 'row' in [0,64), k 'kl' in [0,32)):
//    warp w=row>>4, s=kl>>3, lane=((row&7)<<2)+(kl&3),
//    reg r=((row>>3)&1) + (((kl&7)>=4)?2:0)
//    flat = ((w*4+s)*32 + lane)*4 + r      (separate hi / lo arrays)
//  B element (k 'kl' in [0,32), n in [0,64)):
//    s=kl>>3, nt=n>>3, lane=((n&7)<<2)+(kl&3), reg=((kl&7)>=4)?1:0
//    flat = ((s*8+nt)*32 + lane)*4 + {reg: hi, reg+2: lo}  (interleaved)

// ============================================================
// K0a: row dot products with weight vectors (warp per row)
// ============================================================
__global__ __launch_bounds__(256) void k_dots(
    const float* __restrict__ c, const float* __restrict__ q,
    const float* __restrict__ cw, const float* __restrict__ qw)
{
    int gw   = (blockIdx.x * blockDim.x + threadIdx.x) >> 5;
    int lane = threadIdx.x & 31;
    const int NC = B_ * CL_;
    if (gw >= NC + B_ * QL_) return;

    const float4* row;
    const float4* w;
    if (gw < NC) { row = (const float4*)c + gw * (H_/4);        w = (const float4*)cw; }
    else         { row = (const float4*)q + (gw - NC) * (H_/4); w = (const float4*)qw; }

    float s = 0.f;
#pragma unroll
    for (int r = 0; r < 8; r++) {
        float4 a = row[lane + 32*r];
        float4 b = w  [lane + 32*r];
        s += a.x*b.x + a.y*b.y + a.z*b.z + a.w*b.w;
    }
#pragma unroll
    for (int o = 16; o; o >>= 1) s += __shfl_xor_sync(0xffffffffu, s, o);
    if (lane == 0) {
        if (gw < NC) g_cdot[gw] = s;
        else { int r = gw - NC; g_qdot[(r / QL_) * QS_ + (r % QL_)] = s; }
    }
}

// ============================================================
// K0b: build zero-padded q copy [B,64,H]
// ============================================================
__global__ __launch_bounds__(256) void k_qpad(const float* __restrict__ q)
{
    int idx = blockIdx.x * blockDim.x + threadIdx.x;   // float4 index
    int h4 = idx & 255;
    int j  = (idx >> 8) & 63;
    int b  = idx >> 14;
    float4 v = make_float4(0.f, 0.f, 0.f, 0.f);
    if (j < QL_) v = ((const float4*)q)[((b * QL_ + j) << 8) + h4];
    ((float4*)g_qpad)[idx] = v;
}

// ============================================================
// K1: G[b, i-tile 64, j 64] = (c*cqw) @ qpad^T,  K=H=1024, chunk 32.
// ============================================================
__global__ __launch_bounds__(128) void k_simgemm(
    const float* __restrict__ c, const float* __restrict__ cqw)
{
    __shared__ unsigned AFh[2048], AFl[2048], BF[4096];  // 32 KB

    int b  = blockIdx.y;
    int i0 = blockIdx.x * 64;
    int tid = threadIdx.x, lane = tid & 31, w = tid >> 5;

    const float* cb = c      + (size_t)b * CL_ * H_;
    const float* qb = g_qpad + (size_t)b * QS_ * H_;

    float acc[8][4];
#pragma unroll
    for (int n = 0; n < 8; n++)
#pragma unroll
        for (int r = 0; r < 4; r++) acc[n][r] = 0.f;

    for (int kc = 0; kc < H_; kc += 32) {
        __syncthreads();
        // ---- stage A (64 rows x 32 k of c*cqw) ----
#pragma unroll
        for (int it = 0; it < 4; it++) {
            int p   = tid + 128 * it;
            int row = p >> 3;
            int k4  = (p & 7) * 4;
            float4 v = make_float4(0.f, 0.f, 0.f, 0.f);
            int gi = i0 + row;
            if (gi < CL_) {
                v = *(const float4*)(cb + (size_t)gi * H_ + kc + k4);
                float4 wv = *(const float4*)(cqw + kc + k4);
                v.x *= wv.x; v.y *= wv.y; v.z *= wv.z; v.w *= wv.w;
            }
            int s = k4 >> 3;
            int r = ((row >> 3) & 1) + ((k4 & 4) ? 2 : 0);
            int base = (((row >> 4) * 4 + s) * 32 + ((row & 7) << 2)) * 4 + r;
            unsigned h0_, l0_, h1_, l1_, h2_, l2_, h3_, l3_;
            split1(v.x, h0_, l0_); split1(v.y, h1_, l1_);
            split1(v.z, h2_, l2_); split1(v.w, h3_, l3_);
            AFh[base] = h0_; AFh[base+4] = h1_; AFh[base+8] = h2_; AFh[base+12] = h3_;
            AFl[base] = l0_; AFl[base+4] = l1_; AFl[base+8] = l2_; AFl[base+12] = l3_;
        }
        // ---- stage B (qpad: n=j rows 64, k along h) ----
#pragma unroll
        for (int it = 0; it < 4; it++) {
            int p  = tid + 128 * it;
            int n  = p >> 3;
            int k4 = (p & 7) * 4;
            float4 v = *(const float4*)(qb + (size_t)n * H_ + kc + k4);
            int s = k4 >> 3;
            int breg = (k4 & 4) ? 1 : 0;
            int base = ((s * 8 + (n >> 3)) * 32 + ((n & 7) << 2)) * 4 + breg;
            unsigned hh, ll;
            split1(v.x, hh, ll); BF[base]      = hh; BF[base+2]    = ll;
            split1(v.y, hh, ll); BF[base+4]    = hh; BF[base+6]    = ll;
            split1(v.z, hh, ll); BF[base+8]    = hh; BF[base+10]   = ll;
            split1(v.w, hh, ll); BF[base+12]   = hh; BF[base+14]   = ll;
        }
        __syncthreads();
        // ---- compute ----
#pragma unroll
        for (int s = 0; s < 4; s++) {
            uint4 ah = ((const uint4*)AFh)[(w*4 + s)*32 + lane];
            uint4 al = ((const uint4*)AFl)[(w*4 + s)*32 + lane];
#pragma unroll
            for (int nt = 0; nt < 8; nt++) {
                uint4 bv = ((const uint4*)BF)[(s*8 + nt)*32 + lane];
                mma8(acc[nt], ah, bv.x, bv.y);   // hi*hi
                mma8(acc[nt], ah, bv.z, bv.w);   // hi*lo
                mma8(acc[nt], al, bv.x, bv.y);   // lo*hi
            }
        }
    }

    int g = lane >> 2, t = lane & 3;
    int r0 = i0 + w*16 + g, r1 = r0 + 8;
#pragma unroll
    for (int nt = 0; nt < 8; nt++) {
        int col = nt*8 + 2*t;
        if (r0 < CL_) *(float2*)(g_G + ((size_t)(b*CL_ + r0) << 6) + col)
                        = make_float2(acc[nt][0], acc[nt][1]);
        if (r1 < CL_) *(float2*)(g_G + ((size_t)(b*CL_ + r1) << 6) + col)
                        = make_float2(acc[nt][2], acc[nt][3]);
    }
}

// ============================================================
// K2a: softmax over q dim (warp per (b,i) row). Also zero-pads s1/s2 cols.
// ============================================================
__global__ __launch_bounds__(256) void k_soft1(
    const int* __restrict__ qmask, const float* __restrict__ bias)
{
    int gw   = (blockIdx.x * 256 + threadIdx.x) >> 5;   // row = b*CL + i
    int lane = threadIdx.x & 31;
    if (gw >= B_ * CL_) return;
    int b = gw / CL_;
    float bi = bias[0];
    float cd = g_cdot[gw];
    const float* Grow = g_G + ((size_t)gw << 6);

    int j1 = lane, j2 = lane + 32;
    float v1 = qmask[b * QL_ + j1] ? (Grow[j1] + cd + g_qdot[b*QS_ + j1] + bi) : -1e30f;
    float v2 = -1e38f;
    if (j2 < QL_) v2 = qmask[b * QL_ + j2] ? (Grow[j2] + cd + g_qdot[b*QS_ + j2] + bi) : -1e30f;

    float mx = fmaxf(v1, v2);
#pragma unroll
    for (int o = 16; o; o >>= 1) mx = fmaxf(mx, __shfl_xor_sync(0xffffffffu, mx, o));
    float e1 = expf(v1 - mx);
    float e2 = (j2 < QL_) ? expf(v2 - mx) : 0.f;
    float s = e1 + e2;
#pragma unroll
    for (int o = 16; o; o >>= 1) s += __shfl_xor_sync(0xffffffffu, s, o);
    float inv = 1.f / s;

    float* s1row = g_s1 + ((size_t)gw << 6);
    s1row[j1] = e1 * inv;
    s1row[j2] = (j2 < QL_) ? e2 * inv : 0.f;
    if (j2 >= QL_) g_s2[((size_t)gw << 6) + j2] = 0.f;  // pad s2 cols 50..63
}

// ============================================================
// K2b: softmax over c dim (warp per (b,j) column)
// ============================================================
__global__ __launch_bounds__(256) void k_soft2(
    const int* __restrict__ cmask, const float* __restrict__ bias)
{
    int gw   = (blockIdx.x * 256 + threadIdx.x) >> 5;   // col = b*QL + j
    int lane = threadIdx.x & 31;
    if (gw >= B_ * QL_) return;
    int b = gw / QL_, j = gw % QL_;
    float qd = g_qdot[b*QS_ + j] + bias[0];

    float v[13];
#pragma unroll
    for (int r = 0; r < 13; r++) {
        int i = lane + 32 * r;
        if (i < CL_) {
            float s = g_G[((size_t)(b * CL_ + i) << 6) + j] + g_cdot[b*CL_ + i] + qd;
            v[r] = cmask[b*CL_ + i] ? s : -1e30f;
        } else v[r] = -1e38f;
    }
    float mx = v[0];
#pragma unroll
    for (int r = 1; r < 13; r++) mx = fmaxf(mx, v[r]);
#pragma unroll
    for (int o = 16; o; o >>= 1) mx = fmaxf(mx, __shfl_xor_sync(0xffffffffu, mx, o));

    float e[13], sum = 0.f;
#pragma unroll
    for (int r = 0; r < 13; r++) {
        int i = lane + 32 * r;
        e[r] = (i < CL_) ? expf(v[r] - mx) : 0.f;
        sum += e[r];
    }
#pragma unroll
    for (int o = 16; o; o >>= 1) sum += __shfl_xor_sync(0xffffffffu, sum, o);
    float inv = 1.f / sum;
#pragma unroll
    for (int r = 0; r < 13; r++) {
        int i = lane + 32 * r;
        if (i < CL_) g_s2[((size_t)(b * CL_ + i) << 6) + j] = e[r] * inv;
    }
}

// ============================================================
// K3: t[b, j 64, h-tile 64] = s2^T @ c,  K=CL=400 (13 chunks of 32, zero-fill)
// ============================================================
__global__ __launch_bounds__(128) void k_s2tc(const float* __restrict__ c)
{
    __shared__ unsigned AFh[2048], AFl[2048], BF[4096];  // 32 KB

    int b  = blockIdx.y;
    int h0 = blockIdx.x * 64;
    int tid = threadIdx.x, lane = tid & 31, w = tid >> 5;

    const float* cb = c + (size_t)b * CL_ * H_;

    float acc[8][4];
#pragma unroll
    for (int n = 0; n < 8; n++)
#pragma unroll
        for (int r = 0; r < 4; r++) acc[n][r] = 0.f;

    for (int kc = 0; kc < 416; kc += 32) {
        __syncthreads();
        // ---- stage A = s2^T : element (m=j, k=i). read s2 rows i, 64 j each.
#pragma unroll
        for (int it = 0; it < 4; it++) {
            int p    = tid + 128 * it;
            int il   = p >> 4;           // k within chunk
            int j4   = (p & 15) * 4;     // m
            int gi   = kc + il;
            float4 v = make_float4(0.f, 0.f, 0.f, 0.f);
            if (gi < CL_) v = *(const float4*)(g_s2 + ((size_t)(b*CL_ + gi) << 6) + j4);
            int s = il >> 3;
            int r = ((j4 >> 3) & 1) + (((il & 7) >= 4) ? 2 : 0);
            int base = (((j4 >> 4) * 4 + s) * 32 + ((j4 & 7) << 2) + (il & 3)) * 4 + r;
            unsigned hh, ll;
            split1(v.x, hh, ll); AFh[base]    = hh; AFl[base]    = ll;
            split1(v.y, hh, ll); AFh[base+16] = hh; AFl[base+16] = ll;
            split1(v.z, hh, ll); AFh[base+32] = hh; AFl[base+32] = ll;
            split1(v.w, hh, ll); AFh[base+48] = hh; AFl[base+48] = ll;
        }
        // ---- stage B = c : element (k=i, n=h). read c rows i along h.
#pragma unroll
        for (int it = 0; it < 4; it++) {
            int p  = tid + 128 * it;
            int il = p >> 4;
            int h4 = (p & 15) * 4;
            int gi = kc + il;
            float4 v = make_float4(0.f, 0.f, 0.f, 0.f);
            if (gi < CL_) v = *(const float4*)(cb + (size_t)gi * H_ + h0 + h4);
            int s = il >> 3;
            int breg = ((il & 7) >= 4) ? 1 : 0;
            int base = ((s * 8 + (h4 >> 3)) * 32 + ((h4 & 7) << 2) + (il & 3)) * 4 + breg;
            unsigned hh, ll;
            split1(v.x, hh, ll); BF[base]    = hh; BF[base+2]  = ll;
            split1(v.y, hh, ll); BF[base+16] = hh; BF[base+18] = ll;
            split1(v.z, hh, ll); BF[base+32] = hh; BF[base+34] = ll;
            split1(v.w, hh, ll); BF[base+48] = hh; BF[base+50] = ll;
        }
        __syncthreads();
        // ---- compute ----
#pragma unroll
        for (int s = 0; s < 4; s++) {
            uint4 ah = ((const uint4*)AFh)[(w*4 + s)*32 + lane];
            uint4 al = ((const uint4*)AFl)[(w*4 + s)*32 + lane];
#pragma unroll
            for (int nt = 0; nt < 8; nt++) {
                uint4 bv = ((const uint4*)BF)[(s*8 + nt)*32 + lane];
                mma8(acc[nt], ah, bv.x, bv.y);
                mma8(acc[nt], ah, bv.z, bv.w);
                mma8(acc[nt], al, bv.x, bv.y);
            }
        }
    }

    int g = lane >> 2, t = lane & 3;
    int j0 = w*16 + g, j1 = j0 + 8;
#pragma unroll
    for (int nt = 0; nt < 8; nt++) {
        int col = h0 + nt*8 + 2*t;
        *(float2*)(g_t + (size_t)(b*QS_ + j0) * H_ + col) = make_float2(acc[nt][0], acc[nt][1]);
        *(float2*)(g_t + (size_t)(b*QS_ + j1) * H_ + col) = make_float2(acc[nt][2], acc[nt][3]);
    }
}

// ============================================================
// K4: a = s1 @ qpad, bb = s1 @ t, K=64 (2 chunks), fused epilogue
//     out = [c, a, c*a, c*bb] for tile (i0..i0+63) x (h0..h0+63)
// ============================================================
__global__ __launch_bounds__(128) void k_out(
    const float* __restrict__ c, float* __restrict__ out)
{
    __shared__ unsigned AFh[2048], AFl[2048], BQ[4096], BT[4096];  // 48 KB

    int b  = blockIdx.z;
    int h0 = blockIdx.y * 64;
    int i0 = blockIdx.x * 64;
    int tid = threadIdx.x, lane = tid & 31, w = tid >> 5;

    const float* cb = c + (size_t)b * CL_ * H_;

    float accA[8][4], accB[8][4];
#pragma unroll
    for (int n = 0; n < 8; n++)
#pragma unroll
        for (int r = 0; r < 4; r++) { accA[n][r] = 0.f; accB[n][r] = 0.f; }

    for (int jc = 0; jc < QS_; jc += 32) {
        __syncthreads();
        // ---- stage A = s1 tile (64 i-rows x 32 j) ----
#pragma unroll
        for (int it = 0; it < 4; it++) {
            int p   = tid + 128 * it;
            int row = p >> 3;
            int k4  = (p & 7) * 4;
            float4 v = make_float4(0.f, 0.f, 0.f, 0.f);
            int gi = i0 + row;
            if (gi < CL_) v = *(const float4*)(g_s1 + ((size_t)(b*CL_ + gi) << 6) + jc + k4);
            int s = k4 >> 3;
            int r = ((row >> 3) & 1) + ((k4 & 4) ? 2 : 0);
            int base = (((row >> 4) * 4 + s) * 32 + ((row & 7) << 2)) * 4 + r;
            unsigned hh, ll;
            split1(v.x, hh, ll); AFh[base]    = hh; AFl[base]    = ll;
            split1(v.y, hh, ll); AFh[base+4]  = hh; AFl[base+4]  = ll;
            split1(v.z, hh, ll); AFh[base+8]  = hh; AFl[base+8]  = ll;
            split1(v.w, hh, ll); AFh[base+12] = hh; AFl[base+12] = ll;
        }
        // ---- stage BQ (qpad) and BT (t): element (k=j, n=h) ----
#pragma unroll
        for (int it = 0; it < 4; it++) {
            int p  = tid + 128 * it;
            int jl = p >> 4;
            int h4 = (p & 15) * 4;
            size_t src = (size_t)(b*QS_ + jc + jl) * H_ + h0 + h4;
            float4 vq = *(const float4*)(g_qpad + src);
            float4 vt = *(const float4*)(g_t    + src);
            int s = jl >> 3;
            int breg = ((jl & 7) >= 4) ? 1 : 0;
            int base = ((s * 8 + (h4 >> 3)) * 32 + ((h4 & 7) << 2) + (jl & 3)) * 4 + breg;
            unsigned hh, ll;
            split1(vq.x, hh, ll); BQ[base]    = hh; BQ[base+2]  = ll;
            split1(vq.y, hh, ll); BQ[base+16] = hh; BQ[base+18] = ll;
            split1(vq.z, hh, ll); BQ[base+32] = hh; BQ[base+34] = ll;
            split1(vq.w, hh, ll); BQ[base+48] = hh; BQ[base+50] = ll;
            split1(vt.x, hh, ll); BT[base]    = hh; BT[base+2]  = ll;
            split1(vt.y, hh, ll); BT[base+16] = hh; BT[base+18] = ll;
            split1(vt.z, hh, ll); BT[base+32] = hh; BT[base+34] = ll;
            split1(vt.w, hh, ll); BT[base+48] = hh; BT[base+50] = ll;
        }
        __syncthreads();
        // ---- compute ----
#pragma unroll
        for (int s = 0; s < 4; s++) {
            uint4 ah = ((const uint4*)AFh)[(w*4 + s)*32 + lane];
            uint4 al = ((const uint4*)AFl)[(w*4 + s)*32 + lane];
#pragma unroll
            for (int nt = 0; nt < 8; nt++) {
                uint4 bq = ((const uint4*)BQ)[(s*8 + nt)*32 + lane];
                mma8(accA[nt], ah, bq.x, bq.y);
                mma8(accA[nt], ah, bq.z, bq.w);
                mma8(accA[nt], al, bq.x, bq.y);
                uint4 bt = ((const uint4*)BT)[(s*8 + nt)*32 + lane];
                mma8(accB[nt], ah, bt.x, bt.y);
                mma8(accB[nt], ah, bt.z, bt.w);
                mma8(accB[nt], al, bt.x, bt.y);
            }
        }
    }

    // ---- fused epilogue ----
    int g = lane >> 2, t = lane & 3;
    int r0 = i0 + w*16 + g, r1 = r0 + 8;
#pragma unroll
    for (int nt = 0; nt < 8; nt++) {
        int col = h0 + nt*8 + 2*t;
        if (r0 < CL_) {
            float2 cv = *(const float2*)(cb + (size_t)r0 * H_ + col);
            float2 av = make_float2(accA[nt][0], accA[nt][1]);
            float2 bv = make_float2(accB[nt][0], accB[nt][1]);
            float* o = out + (size_t)(b*CL_ + r0) * (4*H_) + col;
            *(float2*)(o)          = cv;
            *(float2*)(o + H_)     = av;
            *(float2*)(o + 2*H_)   = make_float2(cv.x*av.x, cv.y*av.y);
            *(float2*)(o + 3*H_)   = make_float2(cv.x*bv.x, cv.y*bv.y);
        }
        if (r1 < CL_) {
            float2 cv = *(const float2*)(cb + (size_t)r1 * H_ + col);
            float2 av = make_float2(accA[nt][2], accA[nt][3]);
            float2 bv = make_float2(accB[nt][2], accB[nt][3]);
            float* o = out + (size_t)(b*CL_ + r1) * (4*H_) + col;
            *(float2*)(o)          = cv;
            *(float2*)(o + H_)     = av;
            *(float2*)(o + 2*H_)   = make_float2(cv.x*av.x, cv.y*av.y);
            *(float2*)(o + 3*H_)   = make_float2(cv.x*bv.x, cv.y*bv.y);
        }
    }
}

// ============================================================
extern "C" void kernel_launch(void* const* d_in, const int* in_sizes, int n_in,
                              void* d_out, int out_size)
{
    const float* c    = (const float*)d_in[0];
    const float* q    = (const float*)d_in[1];
    const int*   cmask= (const int*)  d_in[2];
    const int*   qmask= (const int*)  d_in[3];
    const float* cw   = (const float*)d_in[4];
    const float* qw   = (const float*)d_in[5];
    const float* cqw  = (const float*)d_in[6];
    const float* bias = (const float*)d_in[7];
    float* out = (float*)d_out;

    k_dots   <<<3600, 256>>>(c, q, cw, qw);
    k_qpad   <<<4096, 256>>>(q);
    k_simgemm<<<dim3(7, B_), 128>>>(c, cqw);
    k_soft1  <<<3200, 256>>>(qmask, bias);
    k_soft2  <<<400, 256>>>(cmask, bias);
    k_s2tc   <<<dim3(16, B_), 128>>>(c);
    k_out    <<<dim3(7, 16, B_), 128>>>(c, out);
}

// round 6
// speedup vs baseline: 1.3489x; 1.3489x over previous
#include <cuda_runtime.h>
#include <cstdint>

// Attention_18021682774359: BiDAF-style context-query attention.
// B=64, CL=400, QL=50, H=1024. Output [B, CL, 4H] fp32.
//
// Round 6: pure-fp32 FFMA GEMMs tuned for issue efficiency (sm_100a FFMA
// rt=1/SMSP): XOR-swizzled conflict-free smem, double-buffered staging with
// register prefetch (1 barrier/chunk), K4 with whole K=64 resident.

namespace {
constexpr int B_  = 64;
constexpr int CL_ = 400;
constexpr int QL_ = 50;
constexpr int H_  = 1024;
constexpr int QS_ = 64;   // padded QL
}

// -------- scratch (device globals; allocation-free) --------
__device__ float g_G   [B_*CL_*QS_];
__device__ float g_s1  [B_*CL_*QS_];
__device__ float g_s2  [B_*CL_*QS_];
__device__ float g_qpad[B_*QS_*H_];
__device__ float g_t   [B_*QS_*H_];
__device__ float g_cdot[B_*CL_];
__device__ float g_qdot[B_*QS_];

// swizzle: column position of element m (or n) in a k-major smem row k.
// group g = m>>2 is XOR'd with (k>>2)&7; within-group order preserved.
__device__ __forceinline__ int swz(int g, int k) { return ((g ^ ((k >> 2) & 7)) << 2); }

// ============================================================
// K0a: row dot products with weight vectors (warp per row)
// ============================================================
__global__ __launch_bounds__(256) void k_dots(
    const float* __restrict__ c, const float* __restrict__ q,
    const float* __restrict__ cw, const float* __restrict__ qw)
{
    int gw   = (blockIdx.x * blockDim.x + threadIdx.x) >> 5;
    int lane = threadIdx.x & 31;
    const int NC = B_ * CL_;
    if (gw >= NC + B_ * QL_) return;

    const float4* row;
    const float4* w;
    if (gw < NC) { row = (const float4*)c + gw * (H_/4);        w = (const float4*)cw; }
    else         { row = (const float4*)q + (gw - NC) * (H_/4); w = (const float4*)qw; }

    float s = 0.f;
#pragma unroll
    for (int r = 0; r < 8; r++) {
        float4 a = row[lane + 32*r];
        float4 b = w  [lane + 32*r];
        s += a.x*b.x + a.y*b.y + a.z*b.z + a.w*b.w;
    }
#pragma unroll
    for (int o = 16; o; o >>= 1) s += __shfl_xor_sync(0xffffffffu, s, o);
    if (lane == 0) {
        if (gw < NC) g_cdot[gw] = s;
        else { int r = gw - NC; g_qdot[(r / QL_) * QS_ + (r % QL_)] = s; }
    }
}

// ============================================================
// K0b: build zero-padded q copy [B,64,H]
// ============================================================
__global__ __launch_bounds__(256) void k_qpad(const float* __restrict__ q)
{
    int idx = blockIdx.x * blockDim.x + threadIdx.x;   // float4 index
    int h4 = idx & 255;
    int j  = (idx >> 8) & 63;
    int b  = idx >> 14;
    float4 v = make_float4(0.f, 0.f, 0.f, 0.f);
    if (j < QL_) v = ((const float4*)q)[((b * QL_ + j) << 8) + h4];
    ((float4*)g_qpad)[idx] = v;
}

// ============================================================
// K1: G[b, i-tile 64, j 64] = (c*cqw) @ qpad^T, K=1024, chunk 32,
// double-buffered, swizzled smem, micro 4(m)x8(n), 128 threads.
// ============================================================
__global__ __launch_bounds__(128) void k_simgemm(
    const float* __restrict__ c, const float* __restrict__ cqw)
{
    __shared__ float As[2][32][64];
    __shared__ float Bs[2][32][64];
    int b  = blockIdx.y;
    int i0 = blockIdx.x * 64;
    int tid = threadIdx.x;
    int tx = tid & 7;     // n-group: n0 = tx*8
    int ty = tid >> 3;    // m-group: m0 = ty*4  (0..15)
    const float* cb = c      + (size_t)b * CL_ * H_;
    const float* qb = g_qpad + (size_t)b * QS_ * H_;

    float acc[4][8];
#pragma unroll
    for (int i = 0; i < 4; i++)
#pragma unroll
        for (int j = 0; j < 8; j++) acc[i][j] = 0.f;

    const int k4 = tx * 4;       // staging k offset (this thread stores rows k4..k4+3)
    const int sK = tx & 7;       // (k4>>2)&7
    float4 ra[4], rb[4];

    // ---- prologue: load + store chunk 0 ----
#pragma unroll
    for (int it = 0; it < 4; it++) {
        int r = ty + 16 * it;            // 0..63 (m for A, j for B)
        int gi = i0 + r;
        float4 v = make_float4(0.f, 0.f, 0.f, 0.f);
        if (gi < CL_) {
            v = *(const float4*)(cb + (size_t)gi * H_ + k4);
            float4 w = *(const float4*)(cqw + k4);
            v.x *= w.x; v.y *= w.y; v.z *= w.z; v.w *= w.w;
        }
        ra[it] = v;
        rb[it] = *(const float4*)(qb + (size_t)r * H_ + k4);
    }
#pragma unroll
    for (int it = 0; it < 4; it++) {
        int r = ty + 16 * it;
        int col = swz(r >> 2, k4) + (r & 3);
        As[0][k4+0][col] = ra[it].x; As[0][k4+1][col] = ra[it].y;
        As[0][k4+2][col] = ra[it].z; As[0][k4+3][col] = ra[it].w;
        Bs[0][k4+0][col] = rb[it].x; Bs[0][k4+1][col] = rb[it].y;
        Bs[0][k4+2][col] = rb[it].z; Bs[0][k4+3][col] = rb[it].w;
    }
    __syncthreads();

    for (int ch = 0; ch < 32; ch++) {
        int buf = ch & 1;
        if (ch < 31) {
            int kc = (ch + 1) * 32;
#pragma unroll
            for (int it = 0; it < 4; it++) {
                int r = ty + 16 * it;
                int gi = i0 + r;
                float4 v = make_float4(0.f, 0.f, 0.f, 0.f);
                if (gi < CL_) {
                    v = *(const float4*)(cb + (size_t)gi * H_ + kc + k4);
                    float4 w = *(const float4*)(cqw + kc + k4);
                    v.x *= w.x; v.y *= w.y; v.z *= w.z; v.w *= w.w;
                }
                ra[it] = v;
                rb[it] = *(const float4*)(qb + (size_t)r * H_ + kc + k4);
            }
        }
#pragma unroll 8
        for (int kk = 0; kk < 32; kk++) {
            float4 a  = *(const float4*)&As[buf][kk][swz(ty, kk)];
            float4 b0 = *(const float4*)&Bs[buf][kk][swz(tx*2,     kk)];
            float4 b1 = *(const float4*)&Bs[buf][kk][swz(tx*2 + 1, kk)];
            float av[4] = {a.x, a.y, a.z, a.w};
            float bv[8] = {b0.x,b0.y,b0.z,b0.w, b1.x,b1.y,b1.z,b1.w};
#pragma unroll
            for (int ii = 0; ii < 4; ii++)
#pragma unroll
                for (int jj = 0; jj < 8; jj++) acc[ii][jj] += av[ii] * bv[jj];
        }
        if (ch < 31) {
            int nb = buf ^ 1;
#pragma unroll
            for (int it = 0; it < 4; it++) {
                int r = ty + 16 * it;
                int col = swz(r >> 2, k4) + (r & 3);
                As[nb][k4+0][col] = ra[it].x; As[nb][k4+1][col] = ra[it].y;
                As[nb][k4+2][col] = ra[it].z; As[nb][k4+3][col] = ra[it].w;
                Bs[nb][k4+0][col] = rb[it].x; Bs[nb][k4+1][col] = rb[it].y;
                Bs[nb][k4+2][col] = rb[it].z; Bs[nb][k4+3][col] = rb[it].w;
            }
        }
        __syncthreads();
    }

#pragma unroll
    for (int im = 0; im < 4; im++) {
        int gi = i0 + ty * 4 + im;
        if (gi < CL_) {
            float* g = g_G + ((size_t)(b * CL_ + gi) << 6) + tx * 8;
            *(float4*)(g)     = make_float4(acc[im][0], acc[im][1], acc[im][2], acc[im][3]);
            *(float4*)(g + 4) = make_float4(acc[im][4], acc[im][5], acc[im][6], acc[im][7]);
        }
    }
}

// ============================================================
// K2a: softmax over q dim (warp per (b,i) row). Also zero-pads s1/s2 cols.
// ============================================================
__global__ __launch_bounds__(256) void k_soft1(
    const int* __restrict__ qmask, const float* __restrict__ bias)
{
    int gw   = (blockIdx.x * 256 + threadIdx.x) >> 5;
    int lane = threadIdx.x & 31;
    if (gw >= B_ * CL_) return;
    int b = gw / CL_;
    float bi = bias[0];
    float cd = g_cdot[gw];
    const float* Grow = g_G + ((size_t)gw << 6);

    int j1 = lane, j2 = lane + 32;
    float v1 = qmask[b * QL_ + j1] ? (Grow[j1] + cd + g_qdot[b*QS_ + j1] + bi) : -1e30f;
    float v2 = -1e38f;
    if (j2 < QL_) v2 = qmask[b * QL_ + j2] ? (Grow[j2] + cd + g_qdot[b*QS_ + j2] + bi) : -1e30f;

    float mx = fmaxf(v1, v2);
#pragma unroll
    for (int o = 16; o; o >>= 1) mx = fmaxf(mx, __shfl_xor_sync(0xffffffffu, mx, o));
    float e1 = expf(v1 - mx);
    float e2 = (j2 < QL_) ? expf(v2 - mx) : 0.f;
    float s = e1 + e2;
#pragma unroll
    for (int o = 16; o; o >>= 1) s += __shfl_xor_sync(0xffffffffu, s, o);
    float inv = 1.f / s;

    float* s1row = g_s1 + ((size_t)gw << 6);
    s1row[j1] = e1 * inv;
    s1row[j2] = (j2 < QL_) ? e2 * inv : 0.f;
    if (j2 >= QL_) g_s2[((size_t)gw << 6) + j2] = 0.f;
}

// ============================================================
// K2b: softmax over c dim (warp per (b,j) column)
// ============================================================
__global__ __launch_bounds__(256) void k_soft2(
    const int* __restrict__ cmask, const float* __restrict__ bias)
{
    int gw   = (blockIdx.x * 256 + threadIdx.x) >> 5;
    int lane = threadIdx.x & 31;
    if (gw >= B_ * QL_) return;
    int b = gw / QL_, j = gw % QL_;
    float qd = g_qdot[b*QS_ + j] + bias[0];

    float v[13];
#pragma unroll
    for (int r = 0; r < 13; r++) {
        int i = lane + 32 * r;
        if (i < CL_) {
            float s = g_G[((size_t)(b * CL_ + i) << 6) + j] + g_cdot[b*CL_ + i] + qd;
            v[r] = cmask[b*CL_ + i] ? s : -1e30f;
        } else v[r] = -1e38f;
    }
    float mx = v[0];
#pragma unroll
    for (int r = 1; r < 13; r++) mx = fmaxf(mx, v[r]);
#pragma unroll
    for (int o = 16; o; o >>= 1) mx = fmaxf(mx, __shfl_xor_sync(0xffffffffu, mx, o));

    float e[13], sum = 0.f;
#pragma unroll
    for (int r = 0; r < 13; r++) {
        int i = lane + 32 * r;
        e[r] = (i < CL_) ? expf(v[r] - mx) : 0.f;
        sum += e[r];
    }
#pragma unroll
    for (int o = 16; o; o >>= 1) sum += __shfl_xor_sync(0xffffffffu, sum, o);
    float inv = 1.f / sum;
#pragma unroll
    for (int r = 0; r < 13; r++) {
        int i = lane + 32 * r;
        if (i < CL_) g_s2[((size_t)(b * CL_ + i) << 6) + j] = e[r] * inv;
    }
}

// ============================================================
// K3: t[b, j 64, h-tile 64] = s2^T @ c, K=CL (13 chunks of 32),
// double-buffered, all-vector staging, micro 8(m)x4(n), 128 threads.
// ============================================================
__global__ __launch_bounds__(128) void k_s2tc(const float* __restrict__ c)
{
    __shared__ float As[2][32][64];   // [i_local][j] swizzled
    __shared__ float Bs[2][32][64];   // [i_local][h] swizzled
    int b  = blockIdx.y;
    int h0 = blockIdx.x * 64;
    int tid = threadIdx.x;
    int tx = tid >> 3;    // 0..15: n-group (h), n0 = tx*4
    int ty = tid & 7;     // 0..7:  m-group (j), m0 = ty*8

    float acc[8][4];
#pragma unroll
    for (int i = 0; i < 8; i++)
#pragma unroll
        for (int j = 0; j < 4; j++) acc[i][j] = 0.f;

    const int ilb = tid >> 4;          // staging row base: il = ilb + 8*it
    const int x4  = (tid & 15) * 4;    // staged column group*4
    float4 ra[4], rb[4];

    // ---- prologue chunk 0 ----
#pragma unroll
    for (int it = 0; it < 4; it++) {
        int il = ilb + 8 * it;
        int gi = il;                   // kc = 0
        float4 a = make_float4(0.f,0.f,0.f,0.f), v = a;
        if (gi < CL_) {
            a = *(const float4*)(g_s2 + ((size_t)(b*CL_ + gi) << 6) + x4);
            v = *(const float4*)(c + (size_t)(b*CL_ + gi) * H_ + h0 + x4);
        }
        ra[it] = a; rb[it] = v;
    }
#pragma unroll
    for (int it = 0; it < 4; it++) {
        int il = ilb + 8 * it;
        int col = swz(x4 >> 2, il);
        *(float4*)&As[0][il][col] = ra[it];
        *(float4*)&Bs[0][il][col] = rb[it];
    }
    __syncthreads();

    for (int ch = 0; ch < 13; ch++) {
        int buf = ch & 1;
        if (ch < 12) {
            int kc = (ch + 1) * 32;
#pragma unroll
            for (int it = 0; it < 4; it++) {
                int il = ilb + 8 * it;
                int gi = kc + il;
                float4 a = make_float4(0.f,0.f,0.f,0.f), v = a;
                if (gi < CL_) {
                    a = *(const float4*)(g_s2 + ((size_t)(b*CL_ + gi) << 6) + x4);
                    v = *(const float4*)(c + (size_t)(b*CL_ + gi) * H_ + h0 + x4);
                }
                ra[it] = a; rb[it] = v;
            }
        }
#pragma unroll 8
        for (int kk = 0; kk < 32; kk++) {
            float4 a0 = *(const float4*)&As[buf][kk][swz(ty*2,     kk)];
            float4 a1 = *(const float4*)&As[buf][kk][swz(ty*2 + 1, kk)];
            float4 bb = *(const float4*)&Bs[buf][kk][swz(tx,       kk)];
            float av[8] = {a0.x,a0.y,a0.z,a0.w, a1.x,a1.y,a1.z,a1.w};
            float bv[4] = {bb.x, bb.y, bb.z, bb.w};
#pragma unroll
            for (int ii = 0; ii < 8; ii++)
#pragma unroll
                for (int jj = 0; jj < 4; jj++) acc[ii][jj] += av[ii] * bv[jj];
        }
        if (ch < 12) {
            int nb = buf ^ 1;
#pragma unroll
            for (int it = 0; it < 4; it++) {
                int il = ilb + 8 * it;
                int col = swz(x4 >> 2, il);
                *(float4*)&As[nb][il][col] = ra[it];
                *(float4*)&Bs[nb][il][col] = rb[it];
            }
        }
        __syncthreads();
    }

#pragma unroll
    for (int im = 0; im < 8; im++) {
        int j = ty * 8 + im;                    // all 64 valid (padded)
        *(float4*)(g_t + (size_t)(b * QS_ + j) * H_ + h0 + tx * 4)
            = make_float4(acc[im][0], acc[im][1], acc[im][2], acc[im][3]);
    }
}

// ============================================================
// K4: a = s1 @ qpad, bb = s1 @ t (K=64 fully resident), fused epilogue
//     out = [c, a, c*a, c*bb]. Tile 64(i)x64(h), micro 4x8, 128 threads.
// ============================================================
__global__ __launch_bounds__(128) void k_out(
    const float* __restrict__ c, float* __restrict__ out)
{
    __shared__ float As[64][64];   // [j][i_local] swizzled (s1^T)
    __shared__ float BQ[64][64];   // [j][h] swizzled
    __shared__ float BT[64][64];
    int b  = blockIdx.z;
    int h0 = blockIdx.y * 64;
    int i0 = blockIdx.x * 64;
    int tid = threadIdx.x;
    int tx = tid & 7;     // n-group: h0 + tx*8
    int ty = tid >> 3;    // 0..15: m-group: i-run 4 at ty*4
    const float* cb = c + (size_t)b * CL_ * H_;

    // ---- stage A = s1^T (scalar scatter, swizzled -> conflict-light) ----
    {
        int j4 = (tid & 15) * 4;            // k rows j4..j4+3
        int sJ = (j4 >> 2) & 7;
#pragma unroll
        for (int it = 0; it < 8; it++) {
            int il = (tid >> 4) + 8 * it;   // i_local 0..63
            int gi = i0 + il;
            float4 v = make_float4(0.f,0.f,0.f,0.f);
            if (gi < CL_) v = *(const float4*)(g_s1 + ((size_t)(b*CL_ + gi) << 6) + j4);
            int col = (((il >> 2) ^ sJ) << 2) + (il & 3);
            As[j4+0][col] = v.x; As[j4+1][col] = v.y;
            As[j4+2][col] = v.z; As[j4+3][col] = v.w;
        }
    }
    // ---- stage BQ, BT (vector, swizzled) ----
    {
        int h4 = (tid & 15) * 4;
#pragma unroll
        for (int it = 0; it < 8; it++) {
            int jl = (tid >> 4) + 8 * it;   // j row 0..63
            int col = swz(h4 >> 2, jl);
            size_t src = (size_t)(b * QS_ + jl) * H_ + h0 + h4;
            *(float4*)&BQ[jl][col] = *(const float4*)(g_qpad + src);
            *(float4*)&BT[jl][col] = *(const float4*)(g_t + src);
        }
    }
    __syncthreads();

    float accA[4][8], accB[4][8];
#pragma unroll
    for (int i = 0; i < 4; i++)
#pragma unroll
        for (int j = 0; j < 8; j++) { accA[i][j] = 0.f; accB[i][j] = 0.f; }

#pragma unroll 8
    for (int kk = 0; kk < 64; kk++) {
        float4 a  = *(const float4*)&As[kk][swz(ty,       kk)];
        float4 q0 = *(const float4*)&BQ[kk][swz(tx*2,     kk)];
        float4 q1 = *(const float4*)&BQ[kk][swz(tx*2 + 1, kk)];
        float4 t0 = *(const float4*)&BT[kk][swz(tx*2,     kk)];
        float4 t1 = *(const float4*)&BT[kk][swz(tx*2 + 1, kk)];
        float av[4] = {a.x, a.y, a.z, a.w};
        float qv[8] = {q0.x,q0.y,q0.z,q0.w, q1.x,q1.y,q1.z,q1.w};
        float tv[8] = {t0.x,t0.y,t0.z,t0.w, t1.x,t1.y,t1.z,t1.w};
#pragma unroll
        for (int ii = 0; ii < 4; ii++)
#pragma unroll
            for (int jj = 0; jj < 8; jj++) {
                accA[ii][jj] += av[ii] * qv[jj];
                accB[ii][jj] += av[ii] * tv[jj];
            }
    }

    // ---- fused epilogue ----
#pragma unroll
    for (int im = 0; im < 4; im++) {
        int gi = i0 + ty * 4 + im;
        if (gi >= CL_) continue;
        const float* crow = cb + (size_t)gi * H_ + h0 + tx * 8;
        float4 c0 = *(const float4*)(crow);
        float4 c1 = *(const float4*)(crow + 4);
        float4 a0 = make_float4(accA[im][0], accA[im][1], accA[im][2], accA[im][3]);
        float4 a1 = make_float4(accA[im][4], accA[im][5], accA[im][6], accA[im][7]);
        float4 b0 = make_float4(accB[im][0], accB[im][1], accB[im][2], accB[im][3]);
        float4 b1 = make_float4(accB[im][4], accB[im][5], accB[im][6], accB[im][7]);
        float* o = out + (size_t)(b * CL_ + gi) * (4 * H_) + h0 + tx * 8;
        *(float4*)(o)            = c0;
        *(float4*)(o + 4)        = c1;
        *(float4*)(o + H_)       = a0;
        *(float4*)(o + H_ + 4)   = a1;
        *(float4*)(o + 2*H_)     = make_float4(c0.x*a0.x, c0.y*a0.y, c0.z*a0.z, c0.w*a0.w);
        *(float4*)(o + 2*H_ + 4) = make_float4(c1.x*a1.x, c1.y*a1.y, c1.z*a1.z, c1.w*a1.w);
        *(float4*)(o + 3*H_)     = make_float4(c0.x*b0.x, c0.y*b0.y, c0.z*b0.z, c0.w*b0.w);
        *(float4*)(o + 3*H_ + 4) = make_float4(c1.x*b1.x, c1.y*b1.y, c1.z*b1.z, c1.w*b1.w);
    }
}

// ============================================================
extern "C" void kernel_launch(void* const* d_in, const int* in_sizes, int n_in,
                              void* d_out, int out_size)
{
    const float* c    = (const float*)d_in[0];
    const float* q    = (const float*)d_in[1];
    const int*   cmask= (const int*)  d_in[2];
    const int*   qmask= (const int*)  d_in[3];
    const float* cw   = (const float*)d_in[4];
    const float* qw   = (const float*)d_in[5];
    const float* cqw  = (const float*)d_in[6];
    const float* bias = (const float*)d_in[7];
    float* out = (float*)d_out;

    k_dots   <<<3600, 256>>>(c, q, cw, qw);
    k_qpad   <<<4096, 256>>>(q);
    k_simgemm<<<dim3(7, B_), 128>>>(c, cqw);
    k_soft1  <<<3200, 256>>>(qmask, bias);
    k_soft2  <<<400, 256>>>(cmask, bias);
    k_s2tc   <<<dim3(16, B_), 128>>>(c);
    k_out    <<<dim3(7, 16, B_), 128>>>(c, out);
}

// round 7
// speedup vs baseline: 1.6458x; 1.2201x over previous
#include <cuda_runtime.h>
#include <cstdint>

// Attention_18021682774359: BiDAF-style context-query attention.
// B=64, CL=400, QL=50, H=1024. Output [B, CL, 4H] fp32.
//
// Round 7: same fp32 FFMA design as round 6 (swizzled smem, double buffer),
// but all GEMM kernels moved to 256 threads/block with 4x4 micro-tiles to
// double warps/SMSP (3 -> 6+) and cover LDS/LDG latency.

namespace {
constexpr int B_  = 64;
constexpr int CL_ = 400;
constexpr int QL_ = 50;
constexpr int H_  = 1024;
constexpr int QS_ = 64;   // padded QL
}

// -------- scratch (device globals; allocation-free) --------
__device__ float g_G   [B_*CL_*QS_];
__device__ float g_s1  [B_*CL_*QS_];
__device__ float g_s2  [B_*CL_*QS_];
__device__ float g_qpad[B_*QS_*H_];
__device__ float g_t   [B_*QS_*H_];
__device__ float g_cdot[B_*CL_];
__device__ float g_qdot[B_*QS_];

// swizzle: float4-group g XOR'd with (k>>2)&7 -> starting float column
__device__ __forceinline__ int swz(int g, int k) { return ((g ^ ((k >> 2) & 7)) << 2); }

// ============================================================
// K0a: row dot products with weight vectors (warp per row)
// ============================================================
__global__ __launch_bounds__(256) void k_dots(
    const float* __restrict__ c, const float* __restrict__ q,
    const float* __restrict__ cw, const float* __restrict__ qw)
{
    int gw   = (blockIdx.x * blockDim.x + threadIdx.x) >> 5;
    int lane = threadIdx.x & 31;
    const int NC = B_ * CL_;
    if (gw >= NC + B_ * QL_) return;

    const float4* row;
    const float4* w;
    if (gw < NC) { row = (const float4*)c + gw * (H_/4);        w = (const float4*)cw; }
    else         { row = (const float4*)q + (gw - NC) * (H_/4); w = (const float4*)qw; }

    float s = 0.f;
#pragma unroll
    for (int r = 0; r < 8; r++) {
        float4 a = row[lane + 32*r];
        float4 b = w  [lane + 32*r];
        s += a.x*b.x + a.y*b.y + a.z*b.z + a.w*b.w;
    }
#pragma unroll
    for (int o = 16; o; o >>= 1) s += __shfl_xor_sync(0xffffffffu, s, o);
    if (lane == 0) {
        if (gw < NC) g_cdot[gw] = s;
        else { int r = gw - NC; g_qdot[(r / QL_) * QS_ + (r % QL_)] = s; }
    }
}

// ============================================================
// K0b: build zero-padded q copy [B,64,H]
// ============================================================
__global__ __launch_bounds__(256) void k_qpad(const float* __restrict__ q)
{
    int idx = blockIdx.x * blockDim.x + threadIdx.x;
    int h4 = idx & 255;
    int j  = (idx >> 8) & 63;
    int b  = idx >> 14;
    float4 v = make_float4(0.f, 0.f, 0.f, 0.f);
    if (j < QL_) v = ((const float4*)q)[((b * QL_ + j) << 8) + h4];
    ((float4*)g_qpad)[idx] = v;
}

// ============================================================
// K1: G[b, i-tile 64, j 64] = (c*cqw) @ qpad^T, K=1024, chunk 32,
// 256 threads, micro 4x4, double-buffered swizzled smem.
// ============================================================
__global__ __launch_bounds__(256) void k_simgemm(
    const float* __restrict__ c, const float* __restrict__ cqw)
{
    __shared__ float As[2][32][64];   // [k][m] swizzled
    __shared__ float Bs[2][32][64];   // [k][n] swizzled
    int b  = blockIdx.y;
    int i0 = blockIdx.x * 64;
    int tid = threadIdx.x;
    int tx = tid & 15;    // n-group: n0 = tx*4
    int ty = tid >> 4;    // m-group: m0 = ty*4
    const float* cb = c      + (size_t)b * CL_ * H_;
    const float* qb = g_qpad + (size_t)b * QS_ * H_;

    float acc[4][4];
#pragma unroll
    for (int i = 0; i < 4; i++)
#pragma unroll
        for (int j = 0; j < 4; j++) acc[i][j] = 0.f;

    float4 ra[2], rb[2];
    // staging map: idx = tid + 256*it -> r = idx&63 (row), k4g = idx>>6 (0..7)
#pragma unroll
    for (int it = 0; it < 2; it++) {
        int idx = tid + 256 * it;
        int r   = idx & 63;
        int k4  = (idx >> 6) * 4;
        int gi  = i0 + r;
        float4 v = make_float4(0.f, 0.f, 0.f, 0.f);
        if (gi < CL_) {
            v = *(const float4*)(cb + (size_t)gi * H_ + k4);
            float4 w = *(const float4*)(cqw + k4);
            v.x *= w.x; v.y *= w.y; v.z *= w.z; v.w *= w.w;
        }
        ra[it] = v;
        rb[it] = *(const float4*)(qb + (size_t)r * H_ + k4);
    }
#pragma unroll
    for (int it = 0; it < 2; it++) {
        int idx = tid + 256 * it;
        int r   = idx & 63;
        int k4g = idx >> 6;
        int k4  = k4g * 4;
        int col = (((r >> 2) ^ k4g) << 2) + (r & 3);
        As[0][k4+0][col] = ra[it].x; As[0][k4+1][col] = ra[it].y;
        As[0][k4+2][col] = ra[it].z; As[0][k4+3][col] = ra[it].w;
        Bs[0][k4+0][col] = rb[it].x; Bs[0][k4+1][col] = rb[it].y;
        Bs[0][k4+2][col] = rb[it].z; Bs[0][k4+3][col] = rb[it].w;
    }
    __syncthreads();

    for (int ch = 0; ch < 32; ch++) {
        int buf = ch & 1;
        if (ch < 31) {
            int kc = (ch + 1) * 32;
#pragma unroll
            for (int it = 0; it < 2; it++) {
                int idx = tid + 256 * it;
                int r   = idx & 63;
                int k4  = (idx >> 6) * 4;
                int gi  = i0 + r;
                float4 v = make_float4(0.f, 0.f, 0.f, 0.f);
                if (gi < CL_) {
                    v = *(const float4*)(cb + (size_t)gi * H_ + kc + k4);
                    float4 w = *(const float4*)(cqw + kc + k4);
                    v.x *= w.x; v.y *= w.y; v.z *= w.z; v.w *= w.w;
                }
                ra[it] = v;
                rb[it] = *(const float4*)(qb + (size_t)r * H_ + kc + k4);
            }
        }
#pragma unroll 8
        for (int kk = 0; kk < 32; kk++) {
            float4 a = *(const float4*)&As[buf][kk][swz(ty, kk)];
            float4 bb = *(const float4*)&Bs[buf][kk][swz(tx, kk)];
            float av[4] = {a.x, a.y, a.z, a.w};
            float bv[4] = {bb.x, bb.y, bb.z, bb.w};
#pragma unroll
            for (int ii = 0; ii < 4; ii++)
#pragma unroll
                for (int jj = 0; jj < 4; jj++) acc[ii][jj] += av[ii] * bv[jj];
        }
        if (ch < 31) {
            int nb = buf ^ 1;
#pragma unroll
            for (int it = 0; it < 2; it++) {
                int idx = tid + 256 * it;
                int r   = idx & 63;
                int k4g = idx >> 6;
                int k4  = k4g * 4;
                int col = (((r >> 2) ^ k4g) << 2) + (r & 3);
                As[nb][k4+0][col] = ra[it].x; As[nb][k4+1][col] = ra[it].y;
                As[nb][k4+2][col] = ra[it].z; As[nb][k4+3][col] = ra[it].w;
                Bs[nb][k4+0][col] = rb[it].x; Bs[nb][k4+1][col] = rb[it].y;
                Bs[nb][k4+2][col] = rb[it].z; Bs[nb][k4+3][col] = rb[it].w;
            }
        }
        __syncthreads();
    }

#pragma unroll
    for (int im = 0; im < 4; im++) {
        int gi = i0 + ty * 4 + im;
        if (gi < CL_) {
            *(float4*)(g_G + ((size_t)(b * CL_ + gi) << 6) + tx * 4)
                = make_float4(acc[im][0], acc[im][1], acc[im][2], acc[im][3]);
        }
    }
}

// ============================================================
// K2a: softmax over q dim (warp per (b,i) row). Also zero-pads s1/s2 cols.
// ============================================================
__global__ __launch_bounds__(256) void k_soft1(
    const int* __restrict__ qmask, const float* __restrict__ bias)
{
    int gw   = (blockIdx.x * 256 + threadIdx.x) >> 5;
    int lane = threadIdx.x & 31;
    if (gw >= B_ * CL_) return;
    int b = gw / CL_;
    float bi = bias[0];
    float cd = g_cdot[gw];
    const float* Grow = g_G + ((size_t)gw << 6);

    int j1 = lane, j2 = lane + 32;
    float v1 = qmask[b * QL_ + j1] ? (Grow[j1] + cd + g_qdot[b*QS_ + j1] + bi) : -1e30f;
    float v2 = -1e38f;
    if (j2 < QL_) v2 = qmask[b * QL_ + j2] ? (Grow[j2] + cd + g_qdot[b*QS_ + j2] + bi) : -1e30f;

    float mx = fmaxf(v1, v2);
#pragma unroll
    for (int o = 16; o; o >>= 1) mx = fmaxf(mx, __shfl_xor_sync(0xffffffffu, mx, o));
    float e1 = expf(v1 - mx);
    float e2 = (j2 < QL_) ? expf(v2 - mx) : 0.f;
    float s = e1 + e2;
#pragma unroll
    for (int o = 16; o; o >>= 1) s += __shfl_xor_sync(0xffffffffu, s, o);
    float inv = 1.f / s;

    float* s1row = g_s1 + ((size_t)gw << 6);
    s1row[j1] = e1 * inv;
    s1row[j2] = (j2 < QL_) ? e2 * inv : 0.f;
    if (j2 >= QL_) g_s2[((size_t)gw << 6) + j2] = 0.f;
}

// ============================================================
// K2b: softmax over c dim (warp per (b,j) column)
// ============================================================
__global__ __launch_bounds__(256) void k_soft2(
    const int* __restrict__ cmask, const float* __restrict__ bias)
{
    int gw   = (blockIdx.x * 256 + threadIdx.x) >> 5;
    int lane = threadIdx.x & 31;
    if (gw >= B_ * QL_) return;
    int b = gw / QL_, j = gw % QL_;
    float qd = g_qdot[b*QS_ + j] + bias[0];

    float v[13];
#pragma unroll
    for (int r = 0; r < 13; r++) {
        int i = lane + 32 * r;
        if (i < CL_) {
            float s = g_G[((size_t)(b * CL_ + i) << 6) + j] + g_cdot[b*CL_ + i] + qd;
            v[r] = cmask[b*CL_ + i] ? s : -1e30f;
        } else v[r] = -1e38f;
    }
    float mx = v[0];
#pragma unroll
    for (int r = 1; r < 13; r++) mx = fmaxf(mx, v[r]);
#pragma unroll
    for (int o = 16; o; o >>= 1) mx = fmaxf(mx, __shfl_xor_sync(0xffffffffu, mx, o));

    float e[13], sum = 0.f;
#pragma unroll
    for (int r = 0; r < 13; r++) {
        int i = lane + 32 * r;
        e[r] = (i < CL_) ? expf(v[r] - mx) : 0.f;
        sum += e[r];
    }
#pragma unroll
    for (int o = 16; o; o >>= 1) sum += __shfl_xor_sync(0xffffffffu, sum, o);
    float inv = 1.f / sum;
#pragma unroll
    for (int r = 0; r < 13; r++) {
        int i = lane + 32 * r;
        if (i < CL_) g_s2[((size_t)(b * CL_ + i) << 6) + j] = e[r] * inv;
    }
}

// ============================================================
// K3: t[b, j 64, h-tile 64] = s2^T @ c, K=CL (13 chunks of 32),
// 256 threads, micro 4x4, double-buffered swizzled smem.
// ============================================================
__global__ __launch_bounds__(256) void k_s2tc(const float* __restrict__ c)
{
    __shared__ float As[2][32][64];   // [i_local][j] swizzled
    __shared__ float Bs[2][32][64];   // [i_local][h] swizzled
    int b  = blockIdx.y;
    int h0 = blockIdx.x * 64;
    int tid = threadIdx.x;
    int tx = tid & 15;    // n-group (h): n0 = tx*4
    int ty = tid >> 4;    // m-group (j): m0 = ty*4

    float acc[4][4];
#pragma unroll
    for (int i = 0; i < 4; i++)
#pragma unroll
        for (int j = 0; j < 4; j++) acc[i][j] = 0.f;

    float4 ra[2], rb[2];
    // staging map: idx = tid + 256*it -> il = idx>>4 (0..31), x4 = (idx&15)*4
#pragma unroll
    for (int it = 0; it < 2; it++) {
        int idx = tid + 256 * it;
        int il  = idx >> 4;
        int x4  = (idx & 15) * 4;
        int gi  = il;     // kc = 0
        float4 a = make_float4(0.f,0.f,0.f,0.f), v = a;
        if (gi < CL_) {
            a = *(const float4*)(g_s2 + ((size_t)(b*CL_ + gi) << 6) + x4);
            v = *(const float4*)(c + (size_t)(b*CL_ + gi) * H_ + h0 + x4);
        }
        ra[it] = a; rb[it] = v;
    }
#pragma unroll
    for (int it = 0; it < 2; it++) {
        int idx = tid + 256 * it;
        int il  = idx >> 4;
        int x4  = (idx & 15) * 4;
        int col = swz(x4 >> 2, il);
        *(float4*)&As[0][il][col] = ra[it];
        *(float4*)&Bs[0][il][col] = rb[it];
    }
    __syncthreads();

    for (int ch = 0; ch < 13; ch++) {
        int buf = ch & 1;
        if (ch < 12) {
            int kc = (ch + 1) * 32;
#pragma unroll
            for (int it = 0; it < 2; it++) {
                int idx = tid + 256 * it;
                int il  = idx >> 4;
                int x4  = (idx & 15) * 4;
                int gi  = kc + il;
                float4 a = make_float4(0.f,0.f,0.f,0.f), v = a;
                if (gi < CL_) {
                    a = *(const float4*)(g_s2 + ((size_t)(b*CL_ + gi) << 6) + x4);
                    v = *(const float4*)(c + (size_t)(b*CL_ + gi) * H_ + h0 + x4);
                }
                ra[it] = a; rb[it] = v;
            }
        }
#pragma unroll 8
        for (int kk = 0; kk < 32; kk++) {
            float4 a = *(const float4*)&As[buf][kk][swz(ty, kk)];
            float4 bb = *(const float4*)&Bs[buf][kk][swz(tx, kk)];
            float av[4] = {a.x, a.y, a.z, a.w};
            float bv[4] = {bb.x, bb.y, bb.z, bb.w};
#pragma unroll
            for (int ii = 0; ii < 4; ii++)
#pragma unroll
                for (int jj = 0; jj < 4; jj++) acc[ii][jj] += av[ii] * bv[jj];
        }
        if (ch < 12) {
            int nb = buf ^ 1;
#pragma unroll
            for (int it = 0; it < 2; it++) {
                int idx = tid + 256 * it;
                int il  = idx >> 4;
                int x4  = (idx & 15) * 4;
                int col = swz(x4 >> 2, il);
                *(float4*)&As[nb][il][col] = ra[it];
                *(float4*)&Bs[nb][il][col] = rb[it];
            }
        }
        __syncthreads();
    }

#pragma unroll
    for (int im = 0; im < 4; im++) {
        int j = ty * 4 + im;              // all 64 valid (padded)
        *(float4*)(g_t + (size_t)(b * QS_ + j) * H_ + h0 + tx * 4)
            = make_float4(acc[im][0], acc[im][1], acc[im][2], acc[im][3]);
    }
}

// ============================================================
// K4: a = s1 @ qpad, bb = s1 @ t (K=64 fully resident), fused epilogue
//     out = [c, a, c*a, c*bb]. 256 threads, dual micro 4x4.
// ============================================================
__global__ __launch_bounds__(256) void k_out(
    const float* __restrict__ c, float* __restrict__ out)
{
    __shared__ float As[64][64];   // [j][i_local] swizzled (s1^T)
    __shared__ float BQ[64][64];   // [j][h] swizzled
    __shared__ float BT[64][64];
    int b  = blockIdx.z;
    int h0 = blockIdx.y * 64;
    int i0 = blockIdx.x * 64;
    int tid = threadIdx.x;
    int tx = tid & 15;    // n-group: h0 + tx*4
    int ty = tid >> 4;    // m-group: i0 + ty*4
    const float* cb = c + (size_t)b * CL_ * H_;

    // ---- stage A = s1^T (scalar scatter, swizzled) ----
#pragma unroll
    for (int it = 0; it < 4; it++) {
        int idx = tid + 256 * it;
        int il  = idx >> 4;              // i_local 0..63
        int j4  = (idx & 15) * 4;        // j rows j4..j4+3
        int gi  = i0 + il;
        float4 v = make_float4(0.f,0.f,0.f,0.f);
        if (gi < CL_) v = *(const float4*)(g_s1 + ((size_t)(b*CL_ + gi) << 6) + j4);
        int sJ  = (j4 >> 2) & 7;
        int col = (((il >> 2) ^ sJ) << 2) + (il & 3);
        As[j4+0][col] = v.x; As[j4+1][col] = v.y;
        As[j4+2][col] = v.z; As[j4+3][col] = v.w;
    }
    // ---- stage BQ, BT (vector, swizzled) ----
#pragma unroll
    for (int it = 0; it < 4; it++) {
        int idx = tid + 256 * it;
        int jl  = idx >> 4;              // j row 0..63
        int h4  = (idx & 15) * 4;
        int col = swz(h4 >> 2, jl);
        size_t src = (size_t)(b * QS_ + jl) * H_ + h0 + h4;
        *(float4*)&BQ[jl][col] = *(const float4*)(g_qpad + src);
        *(float4*)&BT[jl][col] = *(const float4*)(g_t + src);
    }
    __syncthreads();

    float accA[4][4], accB[4][4];
#pragma unroll
    for (int i = 0; i < 4; i++)
#pragma unroll
        for (int j = 0; j < 4; j++) { accA[i][j] = 0.f; accB[i][j] = 0.f; }

#pragma unroll 8
    for (int kk = 0; kk < 64; kk++) {
        float4 a = *(const float4*)&As[kk][swz(ty, kk)];
        float4 q = *(const float4*)&BQ[kk][swz(tx, kk)];
        float4 t = *(const float4*)&BT[kk][swz(tx, kk)];
        float av[4] = {a.x, a.y, a.z, a.w};
        float qv[4] = {q.x, q.y, q.z, q.w};
        float tv[4] = {t.x, t.y, t.z, t.w};
#pragma unroll
        for (int ii = 0; ii < 4; ii++)
#pragma unroll
            for (int jj = 0; jj < 4; jj++) {
                accA[ii][jj] += av[ii] * qv[jj];
                accB[ii][jj] += av[ii] * tv[jj];
            }
    }

    // ---- fused epilogue ----
#pragma unroll
    for (int im = 0; im < 4; im++) {
        int gi = i0 + ty * 4 + im;
        if (gi >= CL_) continue;
        float4 cv = *(const float4*)(cb + (size_t)gi * H_ + h0 + tx * 4);
        float4 av = make_float4(accA[im][0], accA[im][1], accA[im][2], accA[im][3]);
        float4 bv = make_float4(accB[im][0], accB[im][1], accB[im][2], accB[im][3]);
        float* o = out + (size_t)(b * CL_ + gi) * (4 * H_) + h0 + tx * 4;
        *(float4*)(o)          = cv;
        *(float4*)(o + H_)     = av;
        *(float4*)(o + 2*H_)   = make_float4(cv.x*av.x, cv.y*av.y, cv.z*av.z, cv.w*av.w);
        *(float4*)(o + 3*H_)   = make_float4(cv.x*bv.x, cv.y*bv.y, cv.z*bv.z, cv.w*bv.w);
    }
}

// ============================================================
extern "C" void kernel_launch(void* const* d_in, const int* in_sizes, int n_in,
                              void* d_out, int out_size)
{
    const float* c    = (const float*)d_in[0];
    const float* q    = (const float*)d_in[1];
    const int*   cmask= (const int*)  d_in[2];
    const int*   qmask= (const int*)  d_in[3];
    const float* cw   = (const float*)d_in[4];
    const float* qw   = (const float*)d_in[5];
    const float* cqw  = (const float*)d_in[6];
    const float* bias = (const float*)d_in[7];
    float* out = (float*)d_out;

    k_dots   <<<3600, 256>>>(c, q, cw, qw);
    k_qpad   <<<4096, 256>>>(q);
    k_simgemm<<<dim3(7, B_), 256>>>(c, cqw);
    k_soft1  <<<3200, 256>>>(qmask, bias);
    k_soft2  <<<400, 256>>>(cmask, bias);
    k_s2tc   <<<dim3(16, B_), 256>>>(c);
    k_out    <<<dim3(7, 16, B_), 256>>>(c, out);
}

// round 8
// speedup vs baseline: 1.8656x; 1.1336x over previous
#include <cuda_runtime.h>
#include <cstdint>

// Attention_18021682774359: BiDAF-style context-query attention.
// B=64, CL=400, QL=50, H=1024. Output [B, CL, 4H] fp32.
//
// Round 8: smem-bandwidth rebalance. 8x8 (K1/K3) and dual 8x4 (K4) micro-
// tiles bring shared-memory bytes/FFMA to the 128B/cyc/SM crossbar budget.
// K1 k-vectorized with crosswise swizzle + cp.async (cqw folded into qpadw);
// K3 outer-product with cp.async (both operands k-major in gmem);
// K4 K=64 resident, one-time s1 transpose.

namespace {
constexpr int B_  = 64;
constexpr int CL_ = 400;
constexpr int QL_ = 50;
constexpr int H_  = 1024;
constexpr int QS_ = 64;   // padded QL
}

// -------- scratch (device globals; allocation-free) --------
__device__ float g_G    [B_*CL_*QS_];
__device__ float g_s1   [B_*CL_*QS_];
__device__ float g_s2   [B_*CL_*QS_];
__device__ float g_qpad [B_*QS_*H_];   // raw q, zero-padded rows
__device__ float g_qpadw[B_*QS_*H_];   // q * cqw, zero-padded rows
__device__ float g_t    [B_*QS_*H_];
__device__ float g_cdot [B_*CL_];
__device__ float g_qdot [B_*QS_];

__device__ __forceinline__ unsigned smem_u32(const void* p) {
    return (unsigned)__cvta_generic_to_shared(p);
}
__device__ __forceinline__ void cp_async16(unsigned dst, const void* src, bool pred) {
    int sz = pred ? 16 : 0;
    asm volatile("cp.async.cg.shared.global [%0], [%1], 16, %2;"
                 :: "r"(dst), "l"(src), "r"(sz) : "memory");
}
__device__ __forceinline__ void cp_commit() {
    asm volatile("cp.async.commit_group;" ::: "memory");
}

// ============================================================
// K0a: row dot products with weight vectors (warp per row)
// ============================================================
__global__ __launch_bounds__(256) void k_dots(
    const float* __restrict__ c, const float* __restrict__ q,
    const float* __restrict__ cw, const float* __restrict__ qw)
{
    int gw   = (blockIdx.x * blockDim.x + threadIdx.x) >> 5;
    int lane = threadIdx.x & 31;
    const int NC = B_ * CL_;
    if (gw >= NC + B_ * QL_) return;

    const float4* row;
    const float4* w;
    if (gw < NC) { row = (const float4*)c + gw * (H_/4);        w = (const float4*)cw; }
    else         { row = (const float4*)q + (gw - NC) * (H_/4); w = (const float4*)qw; }

    float s = 0.f;
#pragma unroll
    for (int r = 0; r < 8; r++) {
        float4 a = row[lane + 32*r];
        float4 b = w  [lane + 32*r];
        s += a.x*b.x + a.y*b.y + a.z*b.z + a.w*b.w;
    }
#pragma unroll
    for (int o = 16; o; o >>= 1) s += __shfl_xor_sync(0xffffffffu, s, o);
    if (lane == 0) {
        if (gw < NC) g_cdot[gw] = s;
        else { int r = gw - NC; g_qdot[(r / QL_) * QS_ + (r % QL_)] = s; }
    }
}

// ============================================================
// K0b: build zero-padded q (raw and cqw-scaled) [B,64,H]
// ============================================================
__global__ __launch_bounds__(256) void k_qpad(
    const float* __restrict__ q, const float* __restrict__ cqw)
{
    int idx = blockIdx.x * blockDim.x + threadIdx.x;   // float4 index
    int h4 = idx & 255;
    int j  = (idx >> 8) & 63;
    int b  = idx >> 14;
    float4 v = make_float4(0.f, 0.f, 0.f, 0.f);
    if (j < QL_) v = ((const float4*)q)[((b * QL_ + j) << 8) + h4];
    ((float4*)g_qpad)[idx] = v;
    float4 w = ((const float4*)cqw)[h4];
    ((float4*)g_qpadw)[idx] = make_float4(v.x*w.x, v.y*w.y, v.z*w.z, v.w*w.w);
}

// ============================================================
// K1: G[b, i-tile 64, j 64] = c @ qpadw^T, K=1024.
// 64 threads, micro 8x8 (halves split by +32), k-vectorized inner loop.
// Crosswise swizzle: float4 (row r, kgroup kg) at r*8 + (kg ^ ((r>>2)&7)).
// ============================================================
__global__ __launch_bounds__(64) void k_simgemm(const float* __restrict__ c)
{
    __shared__ float4 As4[2][512];   // 64 rows x 8 kgroups
    __shared__ float4 Bs4[2][512];
    int b  = blockIdx.y;
    int i0 = blockIdx.x * 64;
    int tid = threadIdx.x, tx = tid & 7, ty = tid >> 3;
    const float* cb = c        + (size_t)b * CL_ * H_;
    const float* qb = g_qpadw  + (size_t)b * QS_ * H_;

    float acc[8][8];
#pragma unroll
    for (int i = 0; i < 8; i++)
#pragma unroll
        for (int j = 0; j < 8; j++) acc[i][j] = 0.f;

    auto stage = [&](int ch, int buf) {
        int kc = ch * 32;
#pragma unroll
        for (int u = 0; u < 8; u++) {
            int idx = tid + 64 * u;
            int m = idx >> 3, kg = idx & 7;
            bool p = (i0 + m) < CL_;
            const float* src = cb + (size_t)(p ? (i0 + m) : 0) * H_ + kc + kg * 4;
            cp_async16(smem_u32(&As4[buf][m * 8 + (kg ^ ((m >> 2) & 7))]), src, p);
        }
#pragma unroll
        for (int u = 0; u < 8; u++) {
            int idx = tid + 64 * u;
            int n = idx >> 3, kg = idx & 7;
            cp_async16(smem_u32(&Bs4[buf][n * 8 + (kg ^ ((n >> 2) & 7))]),
                       qb + (size_t)n * H_ + kc + kg * 4, true);
        }
        cp_commit();
    };

    stage(0, 0);
    for (int ch = 0; ch < 32; ch++) {
        int buf = ch & 1;
        if (ch < 31) {
            stage(ch + 1, buf ^ 1);
            asm volatile("cp.async.wait_group 1;" ::: "memory");
        } else {
            asm volatile("cp.async.wait_group 0;" ::: "memory");
        }
        __syncthreads();
#pragma unroll 1
        for (int kg = 0; kg < 8; kg++) {
            float4 a4[8], b4[8];
#pragma unroll
            for (int ii = 0; ii < 4; ii++) {
                a4[ii]     = As4[buf][(ty * 4 + ii)      * 8 + (kg ^ ty)];
                a4[ii + 4] = As4[buf][(ty * 4 + 32 + ii) * 8 + (kg ^ ty)];
                b4[ii]     = Bs4[buf][(tx * 4 + ii)      * 8 + (kg ^ tx)];
                b4[ii + 4] = Bs4[buf][(tx * 4 + 32 + ii) * 8 + (kg ^ tx)];
            }
#pragma unroll
            for (int ii = 0; ii < 8; ii++)
#pragma unroll
                for (int jj = 0; jj < 8; jj++) {
                    acc[ii][jj] += a4[ii].x * b4[jj].x + a4[ii].y * b4[jj].y
                                 + a4[ii].z * b4[jj].z + a4[ii].w * b4[jj].w;
                }
        }
        __syncthreads();
    }

#pragma unroll
    for (int ii = 0; ii < 8; ii++) {
        int gi = i0 + ty * 4 + (ii & 3) + ((ii >= 4) ? 32 : 0);
        if (gi < CL_) {
            float* g = g_G + ((size_t)(b * CL_ + gi) << 6);
            *(float4*)(g + tx * 4)      = make_float4(acc[ii][0], acc[ii][1], acc[ii][2], acc[ii][3]);
            *(float4*)(g + tx * 4 + 32) = make_float4(acc[ii][4], acc[ii][5], acc[ii][6], acc[ii][7]);
        }
    }
}

// ============================================================
// K2a: softmax over q dim (warp per (b,i) row). Also zero-pads s1/s2 cols.
// ============================================================
__global__ __launch_bounds__(256) void k_soft1(
    const int* __restrict__ qmask, const float* __restrict__ bias)
{
    int gw   = (blockIdx.x * 256 + threadIdx.x) >> 5;
    int lane = threadIdx.x & 31;
    if (gw >= B_ * CL_) return;
    int b = gw / CL_;
    float bi = bias[0];
    float cd = g_cdot[gw];
    const float* Grow = g_G + ((size_t)gw << 6);

    int j1 = lane, j2 = lane + 32;
    float v1 = qmask[b * QL_ + j1] ? (Grow[j1] + cd + g_qdot[b*QS_ + j1] + bi) : -1e30f;
    float v2 = -1e38f;
    if (j2 < QL_) v2 = qmask[b * QL_ + j2] ? (Grow[j2] + cd + g_qdot[b*QS_ + j2] + bi) : -1e30f;

    float mx = fmaxf(v1, v2);
#pragma unroll
    for (int o = 16; o; o >>= 1) mx = fmaxf(mx, __shfl_xor_sync(0xffffffffu, mx, o));
    float e1 = expf(v1 - mx);
    float e2 = (j2 < QL_) ? expf(v2 - mx) : 0.f;
    float s = e1 + e2;
#pragma unroll
    for (int o = 16; o; o >>= 1) s += __shfl_xor_sync(0xffffffffu, s, o);
    float inv = 1.f / s;

    float* s1row = g_s1 + ((size_t)gw << 6);
    s1row[j1] = e1 * inv;
    s1row[j2] = (j2 < QL_) ? e2 * inv : 0.f;
    if (j2 >= QL_) g_s2[((size_t)gw << 6) + j2] = 0.f;
}

// ============================================================
// K2b: softmax over c dim (warp per (b,j) column)
// ============================================================
__global__ __launch_bounds__(256) void k_soft2(
    const int* __restrict__ cmask, const float* __restrict__ bias)
{
    int gw   = (blockIdx.x * 256 + threadIdx.x) >> 5;
    int lane = threadIdx.x & 31;
    if (gw >= B_ * QL_) return;
    int b = gw / QL_, j = gw % QL_;
    float qd = g_qdot[b*QS_ + j] + bias[0];

    float v[13];
#pragma unroll
    for (int r = 0; r < 13; r++) {
        int i = lane + 32 * r;
        if (i < CL_) {
            float s = g_G[((size_t)(b * CL_ + i) << 6) + j] + g_cdot[b*CL_ + i] + qd;
            v[r] = cmask[b*CL_ + i] ? s : -1e30f;
        } else v[r] = -1e38f;
    }
    float mx = v[0];
#pragma unroll
    for (int r = 1; r < 13; r++) mx = fmaxf(mx, v[r]);
#pragma unroll
    for (int o = 16; o; o >>= 1) mx = fmaxf(mx, __shfl_xor_sync(0xffffffffu, mx, o));

    float e[13], sum = 0.f;
#pragma unroll
    for (int r = 0; r < 13; r++) {
        int i = lane + 32 * r;
        e[r] = (i < CL_) ? expf(v[r] - mx) : 0.f;
        sum += e[r];
    }
#pragma unroll
    for (int o = 16; o; o >>= 1) sum += __shfl_xor_sync(0xffffffffu, sum, o);
    float inv = 1.f / sum;
#pragma unroll
    for (int r = 0; r < 13; r++) {
        int i = lane + 32 * r;
        if (i < CL_) g_s2[((size_t)(b * CL_ + i) << 6) + j] = e[r] * inv;
    }
}

// ============================================================
// K3: t[b, j 64, h-tile 128] = s2^T @ c, K=CL (13 chunks of 32).
// 128 threads, micro 8x8, outer-product ([k][m], [k][n] layouts, cp.async).
// ============================================================
__global__ __launch_bounds__(128) void k_s2tc(const float* __restrict__ c)
{
    __shared__ float4 As4[2][512];    // [k 32][m-groups 16]
    __shared__ float4 Bs4[2][1024];   // [k 32][n-groups 32]
    int b  = blockIdx.y;
    int h0 = blockIdx.x * 128;
    int tid = threadIdx.x, tx = tid & 15, ty = tid >> 4;

    float acc[8][8];
#pragma unroll
    for (int i = 0; i < 8; i++)
#pragma unroll
        for (int j = 0; j < 8; j++) acc[i][j] = 0.f;

    auto stage = [&](int ch, int buf) {
        int kc = ch * 32;
#pragma unroll
        for (int u = 0; u < 4; u++) {
            int idx = tid + 128 * u;
            int il = idx >> 4, jg = idx & 15;
            bool p = (kc + il) < CL_;
            const float* src = g_s2 + ((size_t)(b * CL_ + (p ? kc + il : 0)) << 6) + jg * 4;
            cp_async16(smem_u32(&As4[buf][il * 16 + (jg ^ ((il >> 2) & 7))]), src, p);
        }
#pragma unroll
        for (int u = 0; u < 8; u++) {
            int idx = tid + 128 * u;
            int il = idx >> 5, hg = idx & 31;
            bool p = (kc + il) < CL_;
            const float* src = c + (size_t)(b * CL_ + (p ? kc + il : 0)) * H_ + h0 + hg * 4;
            cp_async16(smem_u32(&Bs4[buf][il * 32 + (hg ^ ((il >> 2) & 7))]), src, p);
        }
        cp_commit();
    };

    stage(0, 0);
    for (int ch = 0; ch < 13; ch++) {
        int buf = ch & 1;
        if (ch < 12) {
            stage(ch + 1, buf ^ 1);
            asm volatile("cp.async.wait_group 1;" ::: "memory");
        } else {
            asm volatile("cp.async.wait_group 0;" ::: "memory");
        }
        __syncthreads();
#pragma unroll 4
        for (int kk = 0; kk < 32; kk++) {
            int s = (kk >> 2) & 7;
            float4 a0 = As4[buf][kk * 16 + (ty ^ s)];
            float4 a1 = As4[buf][kk * 16 + ((ty + 8) ^ s)];
            float4 b0 = Bs4[buf][kk * 32 + (tx ^ s)];
            float4 b1 = Bs4[buf][kk * 32 + ((tx + 16) ^ s)];
            float av[8] = {a0.x,a0.y,a0.z,a0.w, a1.x,a1.y,a1.z,a1.w};
            float bv[8] = {b0.x,b0.y,b0.z,b0.w, b1.x,b1.y,b1.z,b1.w};
#pragma unroll
            for (int ii = 0; ii < 8; ii++)
#pragma unroll
                for (int jj = 0; jj < 8; jj++) acc[ii][jj] += av[ii] * bv[jj];
        }
        __syncthreads();
    }

#pragma unroll
    for (int ii = 0; ii < 8; ii++) {
        int j = ty * 4 + (ii & 3) + ((ii >= 4) ? 32 : 0);   // all < 64 valid
        float* gt = g_t + (size_t)(b * QS_ + j) * H_ + h0;
        *(float4*)(gt + tx * 4)      = make_float4(acc[ii][0], acc[ii][1], acc[ii][2], acc[ii][3]);
        *(float4*)(gt + tx * 4 + 64) = make_float4(acc[ii][4], acc[ii][5], acc[ii][6], acc[ii][7]);
    }
}

// ============================================================
// K4: a = s1 @ qpad, bb = s1 @ t (K=64 resident), fused epilogue
//     out = [c, a, c*a, c*bb]. 128 threads, dual micro 8x4.
// ============================================================
__global__ __launch_bounds__(128) void k_out(
    const float* __restrict__ c, float* __restrict__ out)
{
    __shared__ float  As[64][64];    // [j][i] swizzled (s1^T)
    __shared__ float4 BQ4[1024];     // [j][h-groups 16]
    __shared__ float4 BT4[1024];
    int b  = blockIdx.z;
    int h0 = blockIdx.y * 64;
    int i0 = blockIdx.x * 64;
    int tid = threadIdx.x, tx = tid & 15, ty = tid >> 4;
    const float* cb = c + (size_t)b * CL_ * H_;

    // ---- stage A = s1^T (one-time transpose scatter) ----
#pragma unroll
    for (int u = 0; u < 8; u++) {
        int idx = tid + 128 * u;
        int il = idx >> 4, jg = idx & 15;
        int gi = i0 + il;
        float4 v = make_float4(0.f, 0.f, 0.f, 0.f);
        if (gi < CL_) v = *(const float4*)(g_s1 + ((size_t)(b * CL_ + gi) << 6) + jg * 4);
        int colb = (((il >> 2) ^ (jg & 7)) << 2) | (il & 3);
        As[jg*4+0][colb] = v.x; As[jg*4+1][colb] = v.y;
        As[jg*4+2][colb] = v.z; As[jg*4+3][colb] = v.w;
    }
    // ---- stage BQ, BT ----
#pragma unroll
    for (int u = 0; u < 8; u++) {
        int idx = tid + 128 * u;
        int jl = idx >> 4, hg = idx & 15;
        size_t src = (size_t)(b * QS_ + jl) * H_ + h0 + hg * 4;
        int d = jl * 16 + (hg ^ ((jl >> 2) & 7));
        BQ4[d] = *(const float4*)(g_qpad + src);
        BT4[d] = *(const float4*)(g_t + src);
    }
    __syncthreads();

    float accA[8][4], accB[8][4];
#pragma unroll
    for (int i = 0; i < 8; i++)
#pragma unroll
        for (int j = 0; j < 4; j++) { accA[i][j] = 0.f; accB[i][j] = 0.f; }

#pragma unroll 4
    for (int kk = 0; kk < 64; kk++) {
        int s = (kk >> 2) & 7;
        float4 a0 = *(const float4*)&As[kk][(ty ^ s) << 2];
        float4 a1 = *(const float4*)&As[kk][((ty + 8) ^ s) << 2];
        float4 q  = BQ4[kk * 16 + (tx ^ s)];
        float4 t  = BT4[kk * 16 + (tx ^ s)];
        float av[8] = {a0.x,a0.y,a0.z,a0.w, a1.x,a1.y,a1.z,a1.w};
        float qv[4] = {q.x, q.y, q.z, q.w};
        float tv[4] = {t.x, t.y, t.z, t.w};
#pragma unroll
        for (int ii = 0; ii < 8; ii++)
#pragma unroll
            for (int jj = 0; jj < 4; jj++) {
                accA[ii][jj] += av[ii] * qv[jj];
                accB[ii][jj] += av[ii] * tv[jj];
            }
    }

    // ---- fused epilogue ----
#pragma unroll
    for (int ii = 0; ii < 8; ii++) {
        int gi = i0 + ty * 4 + (ii & 3) + ((ii >= 4) ? 32 : 0);
        if (gi >= CL_) continue;
        float4 cv = *(const float4*)(cb + (size_t)gi * H_ + h0 + tx * 4);
        float4 av = make_float4(accA[ii][0], accA[ii][1], accA[ii][2], accA[ii][3]);
        float4 bv = make_float4(accB[ii][0], accB[ii][1], accB[ii][2], accB[ii][3]);
        float* o = out + (size_t)(b * CL_ + gi) * (4 * H_) + h0 + tx * 4;
        *(float4*)(o)          = cv;
        *(float4*)(o + H_)     = av;
        *(float4*)(o + 2*H_)   = make_float4(cv.x*av.x, cv.y*av.y, cv.z*av.z, cv.w*av.w);
        *(float4*)(o + 3*H_)   = make_float4(cv.x*bv.x, cv.y*bv.y, cv.z*bv.z, cv.w*bv.w);
    }
}

// ============================================================
extern "C" void kernel_launch(void* const* d_in, const int* in_sizes, int n_in,
                              void* d_out, int out_size)
{
    const float* c    = (const float*)d_in[0];
    const float* q    = (const float*)d_in[1];
    const int*   cmask= (const int*)  d_in[2];
    const int*   qmask= (const int*)  d_in[3];
    const float* cw   = (const float*)d_in[4];
    const float* qw   = (const float*)d_in[5];
    const float* cqw  = (const float*)d_in[6];
    const float* bias = (const float*)d_in[7];
    float* out = (float*)d_out;

    k_dots   <<<3600, 256>>>(c, q, cw, qw);
    k_qpad   <<<4096, 256>>>(q, cqw);
    k_simgemm<<<dim3(7, B_), 64>>>(c);
    k_soft1  <<<3200, 256>>>(qmask, bias);
    k_soft2  <<<400, 256>>>(cmask, bias);
    k_s2tc   <<<dim3(8, B_), 128>>>(c);
    k_out    <<<dim3(7, 16, B_), 128>>>(c, out);
}